// round 7
// baseline (speedup 1.0000x reference)
#include <cuda_runtime.h>
#include <cuda_bf16.h>
#include <mma.h>
#include <cstddef>
#include <cstdint>

using namespace nvcuda;

#define B_ 4
#define T_ 1024
#define D_ 512
#define H_ 16
#define DH_ 32
#define BT_ (B_ * T_)

// ---- scratch (static device globals; no runtime allocation) ----
__device__ float g_qh[BT_ * D_];
__device__ float g_kh[BT_ * D_];
__device__ float g_vh[BT_ * D_];
__device__ float g_ph[BT_ * D_];
__device__ float g_ctx[BT_ * D_];
__device__ float g_P[(size_t)B_ * H_ * T_ * T_];  // 256 MB, unshifted pos scores

__device__ __nv_bfloat16 g_inh[4 * BT_ * D_];   // hi(q,k,v,pos)
__device__ __nv_bfloat16 g_inl[4 * BT_ * D_];   // lo
__device__ __nv_bfloat16 g_wth[3 * D_ * D_];    // hi(Wq^T, Wp^T, Wf^T)  [n][k]
__device__ __nv_bfloat16 g_wtl[3 * D_ * D_];
__device__ __nv_bfloat16 g_ctxh[BT_ * D_];
__device__ __nv_bfloat16 g_ctxl[BT_ * D_];
// post-projection splits
__device__ __nv_bfloat16 g_cqh[BT_ * D_];       // hi(qh + u_bias)
__device__ __nv_bfloat16 g_cql[BT_ * D_];
__device__ __nv_bfloat16 g_khh[BT_ * D_];       // hi(kh)
__device__ __nv_bfloat16 g_khl[BT_ * D_];
__device__ __nv_bfloat16 g_vhh[BT_ * D_];       // hi(vh)
__device__ __nv_bfloat16 g_vhl[BT_ * D_];
__device__ __nv_bfloat16 g_aqh[BT_ * D_];       // hi(qh + v_bias)
__device__ __nv_bfloat16 g_aql[BT_ * D_];
__device__ __nv_bfloat16 g_phh[BT_ * D_];       // hi(ph)
__device__ __nv_bfloat16 g_phl[BT_ * D_];

// =====================================================================
// fp32 -> bf16 hi/lo split converters
// =====================================================================
__device__ __forceinline__ void split_bf16(float x, __nv_bfloat16& h, __nv_bfloat16& l) {
  h = __float2bfloat16(x);
  l = __float2bfloat16(x - __bfloat162float(h));
}

__device__ __forceinline__ void split_store4(float4 x, __nv_bfloat16* Hh,
                                             __nv_bfloat16* Ll, size_t i) {
  __nv_bfloat162 h0, h1, l0, l1;
  split_bf16(x.x, h0.x, l0.x); split_bf16(x.y, h0.y, l0.y);
  split_bf16(x.z, h1.x, l1.x); split_bf16(x.w, h1.y, l1.y);
  *reinterpret_cast<__nv_bfloat162*>(&Hh[i]) = h0;
  *reinterpret_cast<__nv_bfloat162*>(&Hh[i + 2]) = h1;
  *reinterpret_cast<__nv_bfloat162*>(&Ll[i]) = l0;
  *reinterpret_cast<__nv_bfloat162*>(&Ll[i + 2]) = l1;
}

__global__ __launch_bounds__(256) void convert_inputs_kernel(
    const float* __restrict__ q, const float* __restrict__ k,
    const float* __restrict__ v, const float* __restrict__ pos) {
  const int z = blockIdx.y;
  const float* src = (z == 0) ? q : (z == 1) ? k : (z == 2) ? v : pos;
  const size_t i = ((size_t)blockIdx.x * 256 + threadIdx.x) * 4;
  split_store4(*reinterpret_cast<const float4*>(&src[i]),
               g_inh + (size_t)z * BT_ * D_, g_inl + (size_t)z * BT_ * D_, i);
}

__global__ __launch_bounds__(256) void convert_ctx_kernel() {
  const size_t i = ((size_t)blockIdx.x * 256 + threadIdx.x) * 4;
  split_store4(*reinterpret_cast<const float4*>(&g_ctx[i]), g_ctxh, g_ctxl, i);
}

// post-projection splits: z=0 cq(qh+ub), 1 kh, 2 vh, 3 aq(qh+vb), 4 ph
__global__ __launch_bounds__(256) void convert_post_kernel(
    const float* __restrict__ ub, const float* __restrict__ vb) {
  const int z = blockIdx.y;
  const size_t i = ((size_t)blockIdx.x * 256 + threadIdx.x) * 4;
  const int d = (int)(i & (D_ - 1));
  const float* src = (z == 1) ? g_kh : (z == 2) ? g_vh : (z == 4) ? g_ph : g_qh;
  float4 x = *reinterpret_cast<const float4*>(&src[i]);
  if (z == 0 || z == 3) {
    const float* bias = (z == 0) ? ub : vb;
    float4 bb = *reinterpret_cast<const float4*>(&bias[d]);
    x.x += bb.x; x.y += bb.y; x.z += bb.z; x.w += bb.w;
  }
  __nv_bfloat16* Hh = (z == 0) ? g_cqh : (z == 1) ? g_khh : (z == 2) ? g_vhh
                    : (z == 3) ? g_aqh : g_phh;
  __nv_bfloat16* Ll = (z == 0) ? g_cql : (z == 1) ? g_khl : (z == 2) ? g_vhl
                    : (z == 3) ? g_aql : g_phl;
  split_store4(x, Hh, Ll, i);
}

// W [k][n] -> Wt [n][k] hi/lo bf16 (32x32 smem tile transpose)
__global__ __launch_bounds__(256) void convert_w_kernel(
    const float* __restrict__ Wq, const float* __restrict__ Wp,
    const float* __restrict__ Wf) {
  const int z = blockIdx.z;
  const float* W = (z == 0) ? Wq : (z == 1) ? Wp : Wf;
  __nv_bfloat16* Hh = g_wth + (size_t)z * D_ * D_;
  __nv_bfloat16* Ll = g_wtl + (size_t)z * D_ * D_;
  __shared__ float tile[32][33];
  const int tx = threadIdx.x & 31, ty = threadIdx.x >> 5;
  const int k0 = blockIdx.y * 32, n0 = blockIdx.x * 32;
#pragma unroll
  for (int r = 0; r < 4; r++)
    tile[ty + 8 * r][tx] = W[(size_t)(k0 + ty + 8 * r) * D_ + n0 + tx];
  __syncthreads();
#pragma unroll
  for (int r = 0; r < 4; r++) {
    const int n = n0 + ty + 8 * r;
    float x = tile[tx][ty + 8 * r];
    __nv_bfloat16 h, l; split_bf16(x, h, l);
    Hh[(size_t)n * D_ + k0 + tx] = h;
    Ll[(size_t)n * D_ + k0 + tx] = l;
  }
}

// =====================================================================
// wmma split-bf16 GEMM (validated round 6)
// =====================================================================
#define ALD 40

__device__ __forceinline__ void wmma_gemm_body(
    const __nv_bfloat16* __restrict__ Ah, const __nv_bfloat16* __restrict__ Al,
    const __nv_bfloat16* __restrict__ Bh, const __nv_bfloat16* __restrict__ Bl,
    const float* __restrict__ bias, float* __restrict__ C, int m0, int n0) {
  __shared__ __align__(16) char smraw[32768];
  __nv_bfloat16* aH = reinterpret_cast<__nv_bfloat16*>(smraw);
  __nv_bfloat16* aL = aH + 128 * ALD;
  __nv_bfloat16* bH = aL + 128 * ALD;
  __nv_bfloat16* bL = bH + 64 * ALD;

  const int tid = threadIdx.x;
  const int wid = tid >> 5;
  const int wm = wid >> 1, wn = wid & 1;

  wmma::fragment<wmma::accumulator, 16, 16, 16, float> acc[2][2];
#pragma unroll
  for (int i = 0; i < 2; i++)
#pragma unroll
    for (int j = 0; j < 2; j++) wmma::fill_fragment(acc[i][j], 0.f);

  for (int k0 = 0; k0 < 512; k0 += 32) {
#pragma unroll
    for (int r2 = 0; r2 < 2; r2++) {
      const int idx = tid + r2 * 256;
      const int r = idx >> 2, c8 = (idx & 3) * 8;
      const size_t g = (size_t)(m0 + r) * D_ + k0 + c8;
      *reinterpret_cast<uint4*>(&aH[r * ALD + c8]) = *reinterpret_cast<const uint4*>(&Ah[g]);
      *reinterpret_cast<uint4*>(&aL[r * ALD + c8]) = *reinterpret_cast<const uint4*>(&Al[g]);
    }
    {
      const int r = tid >> 2, c8 = (tid & 3) * 8;
      const size_t g = (size_t)(n0 + r) * D_ + k0 + c8;
      *reinterpret_cast<uint4*>(&bH[r * ALD + c8]) = *reinterpret_cast<const uint4*>(&Bh[g]);
      *reinterpret_cast<uint4*>(&bL[r * ALD + c8]) = *reinterpret_cast<const uint4*>(&Bl[g]);
    }
    __syncthreads();
#pragma unroll
    for (int kk = 0; kk < 32; kk += 16) {
      wmma::fragment<wmma::matrix_a, 16, 16, 16, __nv_bfloat16, wmma::row_major> fah[2], fal[2];
      wmma::fragment<wmma::matrix_b, 16, 16, 16, __nv_bfloat16, wmma::col_major> fbh[2], fbl[2];
#pragma unroll
      for (int i = 0; i < 2; i++) {
        wmma::load_matrix_sync(fah[i], &aH[(wm * 32 + i * 16) * ALD + kk], ALD);
        wmma::load_matrix_sync(fal[i], &aL[(wm * 32 + i * 16) * ALD + kk], ALD);
        wmma::load_matrix_sync(fbh[i], &bH[(wn * 32 + i * 16) * ALD + kk], ALD);
        wmma::load_matrix_sync(fbl[i], &bL[(wn * 32 + i * 16) * ALD + kk], ALD);
      }
#pragma unroll
      for (int i = 0; i < 2; i++)
#pragma unroll
        for (int j = 0; j < 2; j++) {
          wmma::mma_sync(acc[i][j], fah[i], fbh[j], acc[i][j]);
          wmma::mma_sync(acc[i][j], fah[i], fbl[j], acc[i][j]);
          wmma::mma_sync(acc[i][j], fal[i], fbh[j], acc[i][j]);
        }
    }
    __syncthreads();
  }

  float* Cs = reinterpret_cast<float*>(smraw);
#pragma unroll
  for (int i = 0; i < 2; i++)
#pragma unroll
    for (int j = 0; j < 2; j++)
      wmma::store_matrix_sync(&Cs[(wm * 32 + i * 16) * 64 + wn * 32 + j * 16],
                              acc[i][j], 64, wmma::mem_row_major);
  __syncthreads();
#pragma unroll
  for (int r2 = 0; r2 < 8; r2++) {
    const int idx = tid + r2 * 256;
    const int row = idx >> 4, c4 = (idx & 15) * 4;
    float4 o = *reinterpret_cast<const float4*>(&Cs[row * 64 + c4]);
    if (bias) {
      float4 bb = *reinterpret_cast<const float4*>(&bias[n0 + c4]);
      o.x += bb.x; o.y += bb.y; o.z += bb.z; o.w += bb.w;
    }
    *reinterpret_cast<float4*>(&C[(size_t)(m0 + row) * D_ + n0 + c4]) = o;
  }
}

__global__ __launch_bounds__(256) void wmma_proj_kernel(const float* __restrict__ bq) {
  const int z = blockIdx.z;
  const __nv_bfloat16* Ah = g_inh + (size_t)z * BT_ * D_;
  const __nv_bfloat16* Al = g_inl + (size_t)z * BT_ * D_;
  const int ws = (z < 3) ? 0 : 1;
  float* C = (z == 0) ? g_qh : (z == 1) ? g_kh : (z == 2) ? g_vh : g_ph;
  wmma_gemm_body(Ah, Al, g_wth + (size_t)ws * D_ * D_, g_wtl + (size_t)ws * D_ * D_,
                 (z < 3) ? bq : nullptr, C, blockIdx.y * 128, blockIdx.x * 64);
}

__global__ __launch_bounds__(256) void wmma_final_kernel(const float* __restrict__ bf,
                                                         float* __restrict__ out) {
  wmma_gemm_body(g_ctxh, g_ctxl, g_wth + (size_t)2 * D_ * D_, g_wtl + (size_t)2 * D_ * D_,
                 bf, out, blockIdx.y * 128, blockIdx.x * 64);
}

// =====================================================================
// wmma pscore (validated round 6)
// =====================================================================
__global__ __launch_bounds__(256) void wmma_pscore_kernel() {
  __shared__ __align__(16) __nv_bfloat16 aH[128 * ALD];
  __shared__ __align__(16) __nv_bfloat16 aL[128 * ALD];
  __shared__ __align__(16) __nv_bfloat16 bH[128 * ALD];
  __shared__ __align__(16) __nv_bfloat16 bL[128 * ALD];

  const int tid = threadIdx.x;
  const int wid = tid >> 5;
  const int wm = wid >> 1, wn = wid & 1;
  const int bz = blockIdx.z, b = bz >> 4, h = bz & 15;
  const int t0 = blockIdx.y * 128, j0 = blockIdx.x * 128;

#pragma unroll
  for (int r2 = 0; r2 < 2; r2++) {
    const int idx = tid + r2 * 256;
    const int r = idx >> 2, c8 = (idx & 3) * 8;
    const size_t ga = (size_t)(b * T_ + t0 + r) * D_ + h * DH_ + c8;
    const size_t gb = (size_t)(b * T_ + j0 + r) * D_ + h * DH_ + c8;
    *reinterpret_cast<uint4*>(&aH[r * ALD + c8]) = *reinterpret_cast<const uint4*>(&g_aqh[ga]);
    *reinterpret_cast<uint4*>(&aL[r * ALD + c8]) = *reinterpret_cast<const uint4*>(&g_aql[ga]);
    *reinterpret_cast<uint4*>(&bH[r * ALD + c8]) = *reinterpret_cast<const uint4*>(&g_phh[gb]);
    *reinterpret_cast<uint4*>(&bL[r * ALD + c8]) = *reinterpret_cast<const uint4*>(&g_phl[gb]);
  }
  __syncthreads();

  wmma::fragment<wmma::accumulator, 16, 16, 16, float> acc[2][4];
#pragma unroll
  for (int i = 0; i < 2; i++)
#pragma unroll
    for (int j = 0; j < 4; j++) wmma::fill_fragment(acc[i][j], 0.f);

#pragma unroll
  for (int kk = 0; kk < 32; kk += 16) {
    wmma::fragment<wmma::matrix_a, 16, 16, 16, __nv_bfloat16, wmma::row_major> fah[2], fal[2];
    wmma::fragment<wmma::matrix_b, 16, 16, 16, __nv_bfloat16, wmma::col_major> fbh[4], fbl[4];
#pragma unroll
    for (int i = 0; i < 2; i++) {
      wmma::load_matrix_sync(fah[i], &aH[(wm * 32 + i * 16) * ALD + kk], ALD);
      wmma::load_matrix_sync(fal[i], &aL[(wm * 32 + i * 16) * ALD + kk], ALD);
    }
#pragma unroll
    for (int j = 0; j < 4; j++) {
      wmma::load_matrix_sync(fbh[j], &bH[(wn * 64 + j * 16) * ALD + kk], ALD);
      wmma::load_matrix_sync(fbl[j], &bL[(wn * 64 + j * 16) * ALD + kk], ALD);
    }
#pragma unroll
    for (int i = 0; i < 2; i++)
#pragma unroll
      for (int j = 0; j < 4; j++) {
        wmma::mma_sync(acc[i][j], fah[i], fbh[j], acc[i][j]);
        wmma::mma_sync(acc[i][j], fah[i], fbl[j], acc[i][j]);
        wmma::mma_sync(acc[i][j], fal[i], fbh[j], acc[i][j]);
      }
  }

#pragma unroll
  for (int i = 0; i < 2; i++)
#pragma unroll
    for (int j = 0; j < 4; j++) {
      float* dst = &g_P[((size_t)bz * T_ + t0 + wm * 32 + i * 16) * T_ + j0 + wn * 64 + j * 16];
      wmma::store_matrix_sync(dst, acc[i][j], T_, wmma::mem_row_major);
    }
}

// =====================================================================
// wmma flash: content score (wmma) + shift(P) + softmax (fixed shift,
// no running max -- scores are O(1) here so exp cannot overflow) + AV (wmma).
// Block = 64 q rows x one (b,h); 16 chunks of 64 keys; 256 threads.
// AV accumulators persist in wmma fragments across all chunks; single
// 1/l normalization at the end.
// =====================================================================
#define SLD 68   // fp32 score tile ld
#define PLD 72   // bf16 prob tile ld
#define CLD 36   // fp32 out tile ld
// dynamic smem layout (bytes):
#define OFF_QH 0
#define OFF_QL (OFF_QH + 64 * ALD * 2)
#define OFF_KH (OFF_QL + 64 * ALD * 2)
#define OFF_KL (OFF_KH + 64 * ALD * 2)
#define OFF_VH (OFF_KL + 64 * ALD * 2)
#define OFF_VL (OFF_VH + 64 * ALD * 2)
#define OFF_SS (OFF_VL + 64 * ALD * 2)
#define OFF_PH (OFF_SS + 64 * SLD * 4)
#define OFF_PL (OFF_PH + 64 * PLD * 2)
#define OFF_LR (OFF_PL + 64 * PLD * 2)
#define FLASH_SMEM (OFF_LR + 64 * 4)

__global__ __launch_bounds__(256) void flash_wmma_kernel() {
  extern __shared__ __align__(16) char sm[];
  __nv_bfloat16* Qh = reinterpret_cast<__nv_bfloat16*>(sm + OFF_QH);
  __nv_bfloat16* Ql = reinterpret_cast<__nv_bfloat16*>(sm + OFF_QL);
  __nv_bfloat16* Kh = reinterpret_cast<__nv_bfloat16*>(sm + OFF_KH);
  __nv_bfloat16* Kl = reinterpret_cast<__nv_bfloat16*>(sm + OFF_KL);
  __nv_bfloat16* Vh = reinterpret_cast<__nv_bfloat16*>(sm + OFF_VH);
  __nv_bfloat16* Vl = reinterpret_cast<__nv_bfloat16*>(sm + OFF_VL);
  float* Ss = reinterpret_cast<float*>(sm + OFF_SS);
  __nv_bfloat16* Ph = reinterpret_cast<__nv_bfloat16*>(sm + OFF_PH);
  __nv_bfloat16* Pl = reinterpret_cast<__nv_bfloat16*>(sm + OFF_PL);
  float* lrow = reinterpret_cast<float*>(sm + OFF_LR);

  const int tid = threadIdx.x;
  const int wid = tid >> 5;
  const int wm = wid >> 1, wn = wid & 1;   // 4 x 2 warp grid
  const int bz = blockIdx.y, b = bz >> 4, h = bz & 15;
  const int t0 = blockIdx.x * 64;
  const float isd = 0.04419417382415922f;  // 1/sqrt(512)

  // load Q tile (64 x 32) hi/lo, resident
  {
    const int r = tid >> 2, c8 = (tid & 3) * 8;
    const size_t g = (size_t)(b * T_ + t0 + r) * D_ + h * DH_ + c8;
    *reinterpret_cast<uint4*>(&Qh[r * ALD + c8]) = *reinterpret_cast<const uint4*>(&g_cqh[g]);
    *reinterpret_cast<uint4*>(&Ql[r * ALD + c8]) = *reinterpret_cast<const uint4*>(&g_cql[g]);
  }

  // epilogue thread mapping: 4 threads per row, 16 cols each
  const int er = tid >> 2, eq = (tid & 3) * 16;
  float lsum = 0.f;

  // AV accumulator: one 16x16 frag per warp (4m x 2n covers 64 x 32)
  wmma::fragment<wmma::accumulator, 16, 16, 16, float> accO;
  wmma::fill_fragment(accO, 0.f);

  for (int c = 0; c < 16; c++) {
    const int s0 = c * 64;
    // load K,V chunk (64 x 32) hi/lo
    {
      const int r = tid >> 2, c8 = (tid & 3) * 8;
      const size_t g = (size_t)(b * T_ + s0 + r) * D_ + h * DH_ + c8;
      *reinterpret_cast<uint4*>(&Kh[r * ALD + c8]) = *reinterpret_cast<const uint4*>(&g_khh[g]);
      *reinterpret_cast<uint4*>(&Kl[r * ALD + c8]) = *reinterpret_cast<const uint4*>(&g_khl[g]);
      *reinterpret_cast<uint4*>(&Vh[r * ALD + c8]) = *reinterpret_cast<const uint4*>(&g_vhh[g]);
      *reinterpret_cast<uint4*>(&Vl[r * ALD + c8]) = *reinterpret_cast<const uint4*>(&g_vhl[g]);
    }
    __syncthreads();

    // ---- QK^T: warp computes 16 x 32 stripe of 64 x 64 S ----
    {
      wmma::fragment<wmma::accumulator, 16, 16, 16, float> accS[2];
      wmma::fill_fragment(accS[0], 0.f);
      wmma::fill_fragment(accS[1], 0.f);
#pragma unroll
      for (int kk = 0; kk < 32; kk += 16) {
        wmma::fragment<wmma::matrix_a, 16, 16, 16, __nv_bfloat16, wmma::row_major> fah, fal;
        wmma::load_matrix_sync(fah, &Qh[(wm * 16) * ALD + kk], ALD);
        wmma::load_matrix_sync(fal, &Ql[(wm * 16) * ALD + kk], ALD);
#pragma unroll
        for (int j = 0; j < 2; j++) {
          wmma::fragment<wmma::matrix_b, 16, 16, 16, __nv_bfloat16, wmma::col_major> fbh, fbl;
          wmma::load_matrix_sync(fbh, &Kh[(wn * 32 + j * 16) * ALD + kk], ALD);
          wmma::load_matrix_sync(fbl, &Kl[(wn * 32 + j * 16) * ALD + kk], ALD);
          wmma::mma_sync(accS[j], fah, fbh, accS[j]);
          wmma::mma_sync(accS[j], fah, fbl, accS[j]);
          wmma::mma_sync(accS[j], fal, fbh, accS[j]);
        }
      }
      wmma::store_matrix_sync(&Ss[(wm * 16) * SLD + wn * 32], accS[0], SLD,
                              wmma::mem_row_major);
      wmma::store_matrix_sync(&Ss[(wm * 16) * SLD + wn * 32 + 16], accS[1], SLD,
                              wmma::mem_row_major);
    }
    __syncthreads();

    // ---- epilogue: +shiftP, scale, exp, split to bf16 ----
    {
      const int t = t0 + er;
      const size_t rowb = ((size_t)bz * T_ + t) * T_;
      float* srow = &Ss[er * SLD + eq];
      __nv_bfloat16* phr = &Ph[er * PLD + eq];
      __nv_bfloat16* plr = &Pl[er * PLD + eq];
#pragma unroll
      for (int j = 0; j < 16; j++) {
        const int s = s0 + eq + j;
        float pv;
        if (s <= t)          pv = g_P[rowb + (s - t + (T_ - 1))];
        else if (s == t + 1) pv = 0.f;
        else                 pv = g_P[rowb + T_ + (s - t - 2)];
        float e = __expf((srow[j] + pv) * isd);
        lsum += e;
        __nv_bfloat16 eh, el; split_bf16(e, eh, el);
        phr[j] = eh; plr[j] = el;
      }
    }
    __syncthreads();

    // ---- AV: warp frag (wm*16 rows) x (wn*16 cols), K = 64 ----
#pragma unroll
    for (int kk = 0; kk < 64; kk += 16) {
      wmma::fragment<wmma::matrix_a, 16, 16, 16, __nv_bfloat16, wmma::row_major> pah, pal;
      wmma::fragment<wmma::matrix_b, 16, 16, 16, __nv_bfloat16, wmma::row_major> fvh, fvl;
      wmma::load_matrix_sync(pah, &Ph[(wm * 16) * PLD + kk], PLD);
      wmma::load_matrix_sync(pal, &Pl[(wm * 16) * PLD + kk], PLD);
      wmma::load_matrix_sync(fvh, &Vh[kk * ALD + wn * 16], ALD);
      wmma::load_matrix_sync(fvl, &Vl[kk * ALD + wn * 16], ALD);
      wmma::mma_sync(accO, pah, fvh, accO);
      wmma::mma_sync(accO, pah, fvl, accO);
      wmma::mma_sync(accO, pal, fvh, accO);
    }
    __syncthreads();
  }

  // ---- finalize: row sums across the 4 epilogue threads, normalize ----
  {
    float l = lsum;
    l += __shfl_xor_sync(0xffffffffu, l, 1);
    l += __shfl_xor_sync(0xffffffffu, l, 2);
    if ((tid & 3) == 0) lrow[er] = 1.0f / l;
  }
  // stage AV frags through Ss region as 64 x 32 (ld CLD)
  float* Cs = Ss;
  wmma::store_matrix_sync(&Cs[(wm * 16) * CLD + wn * 16], accO, CLD,
                          wmma::mem_row_major);
  __syncthreads();
  {
    const int row = tid >> 2, c8 = (tid & 3) * 8;
    const float inv = lrow[row];
    float4 a = *reinterpret_cast<const float4*>(&Cs[row * CLD + c8]);
    float4 bb = *reinterpret_cast<const float4*>(&Cs[row * CLD + c8 + 4]);
    a.x *= inv; a.y *= inv; a.z *= inv; a.w *= inv;
    bb.x *= inv; bb.y *= inv; bb.z *= inv; bb.w *= inv;
    const size_t base = (size_t)(b * T_ + t0 + row) * D_ + h * DH_ + c8;
    *reinterpret_cast<float4*>(&g_ctx[base]) = a;
    *reinterpret_cast<float4*>(&g_ctx[base + 4]) = bb;
  }
}

// =====================================================================
extern "C" void kernel_launch(void* const* d_in, const int* in_sizes, int n_in,
                              void* d_out, int out_size) {
  const float* q   = (const float*)d_in[0];
  const float* k   = (const float*)d_in[1];
  const float* v   = (const float*)d_in[2];
  const float* pos = (const float*)d_in[3];
  const float* Wq  = (const float*)d_in[4];
  const float* bq  = (const float*)d_in[5];
  const float* Wp  = (const float*)d_in[6];
  const float* Wf  = (const float*)d_in[7];
  const float* bf  = (const float*)d_in[8];
  const float* ub  = (const float*)d_in[9];
  const float* vb  = (const float*)d_in[10];
  float* out = (float*)d_out;

  static bool attr_done = false;
  if (!attr_done) {
    cudaFuncSetAttribute(flash_wmma_kernel,
                         cudaFuncAttributeMaxDynamicSharedMemorySize, FLASH_SMEM);
    attr_done = true;
  }

  convert_inputs_kernel<<<dim3(BT_ * D_ / 1024, 4), 256>>>(q, k, v, pos);
  convert_w_kernel<<<dim3(16, 16, 3), 256>>>(Wq, Wp, Wf);

  wmma_proj_kernel<<<dim3(8, 32, 4), 256>>>(bq);

  convert_post_kernel<<<dim3(BT_ * D_ / 1024, 5), 256>>>(ub, vb);

  wmma_pscore_kernel<<<dim3(8, 8, 64), 256>>>();

  flash_wmma_kernel<<<dim3(16, 64), 256, FLASH_SMEM>>>();

  convert_ctx_kernel<<<BT_ * D_ / 1024, 256>>>();
  wmma_final_kernel<<<dim3(8, 32), 256>>>(bf, out);
}